// round 16
// baseline (speedup 1.0000x reference)
#include <cuda_runtime.h>
#include <cstdint>

#define NMAX 50000
#define EMAX 1600000
#define HD   128

// ---------------- device scratch (static allocation, no cudaMalloc) ----------
__device__ int   g_deg[NMAX];          // real in-edges (no self-loop)
__device__ float g_dinv[NMAX];         // rsqrt(deg+1)
__device__ int   g_rowptr[NMAX + 1];
__device__ int   g_fill[NMAX];
__device__ int   g_col[EMAX];
__device__ int   g_bsum[64];           // per-block scan totals (<= 49 used)
__device__ float g_hs[(size_t)NMAX * HD];  // raw h = A @ W (gather source)
__device__ float g_h [(size_t)NMAX * HD];  // layer output

// ---------------- degree ----------------------------------------------------
__global__ void k_deg_zero(int n) {
    int i = blockIdx.x * blockDim.x + threadIdx.x;
    if (i < n) g_deg[i] = 0;
}

__global__ void k_deg_count(const int* __restrict__ dst, int e, int n) {
    int i = blockIdx.x * blockDim.x + threadIdx.x;
    if (i < e) {
        int d = dst[i];
        if ((unsigned)d < (unsigned)n) atomicAdd(&g_deg[d], 1);
    }
}

// ---------------- parallel exclusive scan of deg (2 kernels) ----------------
// scan1: warp-shuffle per-block scan -> partial rowptr + block totals + dinv
__global__ __launch_bounds__(1024) void k_scan1(int n) {
    __shared__ int wsum[32];
    int tid = threadIdx.x;
    int lane = tid & 31;
    int wid = tid >> 5;
    int i = blockIdx.x * 1024 + tid;
    int v = (i < n) ? g_deg[i] : 0;
    if (i < n) g_dinv[i] = rsqrtf((float)(v + 1));   // +1 self-loop
    // warp inclusive scan
    int inc = v;
#pragma unroll
    for (int o = 1; o < 32; o <<= 1) {
        int t = __shfl_up_sync(0xffffffffu, inc, o);
        if (lane >= o) inc += t;
    }
    if (lane == 31) wsum[wid] = inc;
    __syncthreads();
    if (wid == 0) {
        int wv = wsum[lane];
        int winc = wv;
#pragma unroll
        for (int o = 1; o < 32; o <<= 1) {
            int t = __shfl_up_sync(0xffffffffu, winc, o);
            if (lane >= o) winc += t;
        }
        wsum[lane] = winc - wv;   // exclusive warp offset
    }
    __syncthreads();
    int excl = (inc - v) + wsum[wid];
    if (i < n) g_rowptr[i] = excl;
    if (tid == 1023) g_bsum[blockIdx.x] = excl + v;   // block total
}

// scan3: parallel reduce of block totals, finalize rowptr + fill cursors
__global__ __launch_bounds__(1024) void k_scan3(int n) {
    __shared__ int off_s;
    int tid = threadIdx.x;
    if (tid < 32) {
        int bid = (int)blockIdx.x;
        int v = 0;
        if (tid < bid) v = g_bsum[tid];
        if (tid + 32 < bid) v += g_bsum[tid + 32];
#pragma unroll
        for (int o = 16; o >= 1; o >>= 1) v += __shfl_xor_sync(0xffffffffu, v, o);
        if (tid == 0) off_s = v;
    }
    __syncthreads();
    int i = blockIdx.x * 1024 + tid;
    if (i >= n) return;
    int rp = g_rowptr[i] + off_s;
    g_rowptr[i] = rp;
    g_fill[i] = rp;
    if (i == n - 1) g_rowptr[n] = rp + g_deg[i];
}

__global__ void k_fill(const int* __restrict__ src,
                       const int* __restrict__ dst, int e, int n) {
    int i = blockIdx.x * blockDim.x + threadIdx.x;
    if (i >= e) return;
    int d = dst[i];
    int s = src[i];
    if ((unsigned)d >= (unsigned)n || (unsigned)s >= (unsigned)n) return;
    int pos = atomicAdd(&g_fill[d], 1);
    if (pos < EMAX) g_col[pos] = s;
}

// ---------------- GEMM: g_hs = A @ W  (M x 128 @ 128 x 128), exact fp32 -----
// 128x128 block tile, 256 threads, 8x8 register tile, fma.rn.f32x2 (FFMA2).
template <int SRC>
__global__ __launch_bounds__(256) void k_gemm(const float* __restrict__ Ax,
                                              const float* __restrict__ W, int M) {
    const float* __restrict__ A = (SRC == 0) ? Ax : g_h;
    __shared__ float XsT[32][132];   // [k][m], padded
    __shared__ float Ws[32][128];    // [k][n]
    int tid = threadIdx.x;
    int row0 = blockIdx.x * 128;
    int tr = tid >> 4;    // 0..15 -> rows tr*8..tr*8+7
    int tc = tid & 15;    // 0..15 -> cols tc*8..tc*8+7

    unsigned long long acc[8][4];    // [i][j2]: packed pair of adjacent columns
#pragma unroll
    for (int i = 0; i < 8; i++)
#pragma unroll
        for (int j = 0; j < 4; j++) acc[i][j] = 0ULL;

    for (int k0 = 0; k0 < 128; k0 += 32) {
#pragma unroll
        for (int l = 0; l < 4; l++) {
            int f = tid + l * 256;        // 0..1023
            int k4 = f >> 7;              // 0..7 (k-group of 4)
            int m = f & 127;              // row within tile
            int grow = row0 + m;
            float4 v = make_float4(0.f, 0.f, 0.f, 0.f);
            if (grow < M) v = *(const float4*)&A[(size_t)grow * 128 + k0 + (k4 << 2)];
            XsT[(k4 << 2) + 0][m] = v.x;
            XsT[(k4 << 2) + 1][m] = v.y;
            XsT[(k4 << 2) + 2][m] = v.z;
            XsT[(k4 << 2) + 3][m] = v.w;
        }
#pragma unroll
        for (int l = 0; l < 4; l++) {
            int f = tid + l * 256;        // 0..1023
            int r = f >> 5;
            int c = (f & 31) << 2;
            *(float4*)&Ws[r][c] = *(const float4*)&W[(size_t)(k0 + r) * 128 + c];
        }
        __syncthreads();
#pragma unroll
        for (int kk = 0; kk < 32; kk++) {
            float a8[8];
            *(float4*)&a8[0] = *(const float4*)&XsT[kk][tr * 8];
            *(float4*)&a8[4] = *(const float4*)&XsT[kk][tr * 8 + 4];
            ulonglong2 t0 = *(const ulonglong2*)&Ws[kk][tc * 8];
            ulonglong2 t1 = *(const ulonglong2*)&Ws[kk][tc * 8 + 4];
            unsigned long long b4[4] = {t0.x, t0.y, t1.x, t1.y};
#pragma unroll
            for (int i = 0; i < 8; i++) {
                unsigned long long aa;
                unsigned int ai = __float_as_uint(a8[i]);
                asm("mov.b64 %0, {%1, %1};" : "=l"(aa) : "r"(ai));
#pragma unroll
                for (int j = 0; j < 4; j++)
                    asm("fma.rn.f32x2 %0, %1, %2, %3;"
                        : "=l"(acc[i][j])
                        : "l"(aa), "l"(b4[j]), "l"(acc[i][j]));
            }
        }
        __syncthreads();
    }
#pragma unroll
    for (int i = 0; i < 8; i++) {
        int row = row0 + tr * 8 + i;
        if (row < M) {
            *(ulonglong2*)&g_hs[(size_t)row * 128 + tc * 8] =
                make_ulonglong2(acc[i][0], acc[i][1]);
            *(ulonglong2*)&g_hs[(size_t)row * 128 + tc * 8 + 4] =
                make_ulonglong2(acc[i][2], acc[i][3]);
        }
    }
}

// ---------------- aggregation: one warp per node, CSR gather ----------------
// Single predicated 8-wide loop; partial groups pad with idx=node, weight 0.
__global__ __launch_bounds__(256) void k_agg(const float* __restrict__ bias, int n) {
    int node = (int)((blockIdx.x * blockDim.x + threadIdx.x) >> 5);
    int lane = threadIdx.x & 31;
    if (node >= n) return;
    const float4* __restrict__ hs4 = (const float4*)g_hs;
    float dn = g_dinv[node];
    float4 hv = hs4[(size_t)node * 32 + lane];   // self-loop term
    float4 acc;
    acc.x = __fmul_rn(hv.x, dn);
    acc.y = __fmul_rn(hv.y, dn);
    acc.z = __fmul_rn(hv.z, dn);
    acc.w = __fmul_rn(hv.w, dn);
    int beg = __ldg(&g_rowptr[node]);
    int end = __ldg(&g_rowptr[node + 1]);
    for (int e = beg; e < end; e += 8) {
        int lim = end - e;                  // >= 1
        int   s[8];
        float d[8];
        float4 v[8];
#pragma unroll
        for (int u = 0; u < 8; u++) {
            int idx = node;                 // safe pad index
            if (u < lim) idx = __ldg(&g_col[e + u]);
            s[u] = idx;
        }
#pragma unroll
        for (int u = 0; u < 8; u++) {
            float dd = __ldg(&g_dinv[s[u]]);
            d[u] = (u < lim) ? dd : 0.f;    // zero weight for padding
        }
#pragma unroll
        for (int u = 0; u < 8; u++) v[u] = __ldg(&hs4[(size_t)s[u] * 32 + lane]);
        float4 p0, p1;
        p0.x = (__fmul_rn(v[0].x, d[0]) + __fmul_rn(v[1].x, d[1])) + (__fmul_rn(v[2].x, d[2]) + __fmul_rn(v[3].x, d[3]));
        p0.y = (__fmul_rn(v[0].y, d[0]) + __fmul_rn(v[1].y, d[1])) + (__fmul_rn(v[2].y, d[2]) + __fmul_rn(v[3].y, d[3]));
        p0.z = (__fmul_rn(v[0].z, d[0]) + __fmul_rn(v[1].z, d[1])) + (__fmul_rn(v[2].z, d[2]) + __fmul_rn(v[3].z, d[3]));
        p0.w = (__fmul_rn(v[0].w, d[0]) + __fmul_rn(v[1].w, d[1])) + (__fmul_rn(v[2].w, d[2]) + __fmul_rn(v[3].w, d[3]));
        p1.x = (__fmul_rn(v[4].x, d[4]) + __fmul_rn(v[5].x, d[5])) + (__fmul_rn(v[6].x, d[6]) + __fmul_rn(v[7].x, d[7]));
        p1.y = (__fmul_rn(v[4].y, d[4]) + __fmul_rn(v[5].y, d[5])) + (__fmul_rn(v[6].y, d[6]) + __fmul_rn(v[7].y, d[7]));
        p1.z = (__fmul_rn(v[4].z, d[4]) + __fmul_rn(v[5].z, d[5])) + (__fmul_rn(v[6].z, d[6]) + __fmul_rn(v[7].z, d[7]));
        p1.w = (__fmul_rn(v[4].w, d[4]) + __fmul_rn(v[5].w, d[5])) + (__fmul_rn(v[6].w, d[6]) + __fmul_rn(v[7].w, d[7]));
        acc.x += p0.x + p1.x;
        acc.y += p0.y + p1.y;
        acc.z += p0.z + p1.z;
        acc.w += p0.w + p1.w;
    }
    float4 bb = __ldg(&((const float4*)bias)[lane]);
    float4 o;
    o.x = fmaxf(fmaf(dn, acc.x, bb.x), 0.f);
    o.y = fmaxf(fmaf(dn, acc.y, bb.y), 0.f);
    o.z = fmaxf(fmaf(dn, acc.z, bb.z), 0.f);
    o.w = fmaxf(fmaf(dn, acc.w, bb.w), 0.f);
    ((float4*)g_h)[(size_t)node * 32 + lane] = o;
}

// ---------------- final: out = g_h @ Wc + bc  (M x 128 @ 128 x 16) ----------
__global__ __launch_bounds__(128) void k_final(const float* __restrict__ Wc,
                                               const float* __restrict__ bc,
                                               float* __restrict__ Out, int M) {
    __shared__ float Ws[128 * 16];
    __shared__ float bs[16];
    int tid = threadIdx.x;
    for (int i = tid; i < 128 * 16; i += 128) Ws[i] = Wc[i];
    if (tid < 16) bs[tid] = bc[tid];
    __syncthreads();
    int row = blockIdx.x * 128 + tid;
    if (row >= M) return;
    float acc[16];
#pragma unroll
    for (int j = 0; j < 16; j++) acc[j] = bs[j];
    const float4* h4 = (const float4*)(g_h + (size_t)row * 128);
#pragma unroll 4
    for (int k4 = 0; k4 < 32; k4++) {
        float4 xv = h4[k4];
#pragma unroll
        for (int kk = 0; kk < 4; kk++) {
            float xs = (kk == 0) ? xv.x : (kk == 1) ? xv.y : (kk == 2) ? xv.z : xv.w;
            int k = k4 * 4 + kk;
            float4 w0 = *(const float4*)&Ws[k * 16 + 0];
            float4 w1 = *(const float4*)&Ws[k * 16 + 4];
            float4 w2 = *(const float4*)&Ws[k * 16 + 8];
            float4 w3 = *(const float4*)&Ws[k * 16 + 12];
            acc[0]  += xs * w0.x; acc[1]  += xs * w0.y; acc[2]  += xs * w0.z; acc[3]  += xs * w0.w;
            acc[4]  += xs * w1.x; acc[5]  += xs * w1.y; acc[6]  += xs * w1.z; acc[7]  += xs * w1.w;
            acc[8]  += xs * w2.x; acc[9]  += xs * w2.y; acc[10] += xs * w2.z; acc[11] += xs * w2.w;
            acc[12] += xs * w3.x; acc[13] += xs * w3.y; acc[14] += xs * w3.z; acc[15] += xs * w3.w;
        }
    }
    float4* o4 = (float4*)(Out + (size_t)row * 16);
    o4[0] = make_float4(acc[0], acc[1], acc[2], acc[3]);
    o4[1] = make_float4(acc[4], acc[5], acc[6], acc[7]);
    o4[2] = make_float4(acc[8], acc[9], acc[10], acc[11]);
    o4[3] = make_float4(acc[12], acc[13], acc[14], acc[15]);
}

// ---------------- launcher (R8 structure: prep ∥ gemm1) ----------------------
extern "C" void kernel_launch(void* const* d_in, const int* in_sizes, int n_in,
                              void* d_out, int out_size) {
    const float* x  = (const float*)d_in[0];
    const int*   ei = (const int*)d_in[1];      // int32 (JAX demotes int64)
    const float* W1 = (const float*)d_in[2];
    const float* b1 = (const float*)d_in[3];
    const float* W2 = (const float*)d_in[4];
    const float* b2 = (const float*)d_in[5];
    const float* Wc = (const float*)d_in[6];
    const float* bc = (const float*)d_in[7];
    float* out = (float*)d_out;

    int n = in_sizes[0] / HD;       // 50000
    int e = in_sizes[1] / 2;        // 1600000
    const int* srcp = ei;
    const int* dstp = ei + e;

    int gn256 = (n + 255) / 256;
    int ge256 = (e + 255) / 256;
    int nb = (n + 1023) / 1024;     // 49 scan blocks

    // one-time host-side stream/event setup (identical GPU work every call)
    static cudaStream_t s_side = (cudaStream_t)0;
    static cudaEvent_t  ev_fork = nullptr, ev_join = nullptr;
    static int s_init = 0;
    if (!s_init) {
        cudaStream_t st;
        cudaEvent_t e0, e1;
        if (cudaStreamCreateWithFlags(&st, cudaStreamNonBlocking) == cudaSuccess &&
            cudaEventCreateWithFlags(&e0, cudaEventDisableTiming) == cudaSuccess &&
            cudaEventCreateWithFlags(&e1, cudaEventDisableTiming) == cudaSuccess) {
            s_side = st; ev_fork = e0; ev_join = e1;
        }
        s_init = 1;
    }
    cudaStream_t sp = s_side;           // prep stream (falls back to 0)
    bool overlap = (s_side != (cudaStream_t)0);

    if (overlap) {
        cudaEventRecord(ev_fork, 0);
        cudaStreamWaitEvent(s_side, ev_fork, 0);
    }

    // CSR build on side stream (runs concurrently with gemm1)
    k_deg_zero<<<gn256, 256, 0, sp>>>(n);
    k_deg_count<<<ge256, 256, 0, sp>>>(dstp, e, n);
    k_scan1<<<nb, 1024, 0, sp>>>(n);
    k_scan3<<<nb, 1024, 0, sp>>>(n);
    k_fill<<<ge256, 256, 0, sp>>>(srcp, dstp, e, n);

    if (overlap) cudaEventRecord(ev_join, s_side);

    int gemm_blocks = (n + 127) / 128;
    int agg_blocks  = (n + 7) / 8;      // 8 warps (nodes) per 256-thread block

    // layer 1 (gemm1 independent of CSR build)
    k_gemm<0><<<gemm_blocks, 256>>>(x, W1, n);
    if (overlap) cudaStreamWaitEvent(0, ev_join, 0);
    k_agg<<<agg_blocks, 256>>>(b1, n);
    // layer 2
    k_gemm<1><<<gemm_blocks, 256>>>(x, W2, n);
    k_agg<<<agg_blocks, 256>>>(b2, n);
    // classifier head
    k_final<<<(n + 127) / 128, 128>>>(Wc, bc, out, n);
}

// round 17
// speedup vs baseline: 1.0498x; 1.0498x over previous
#include <cuda_runtime.h>
#include <cstdint>

#define NMAX 50000
#define EMAX 1600000
#define HD   128

// ---------------- device scratch (static allocation, no cudaMalloc) ----------
__device__ int   g_deg[NMAX];          // real in-edges (no self-loop)
__device__ float g_dinv[NMAX];         // rsqrt(deg+1)
__device__ int   g_rowptr[NMAX + 1];
__device__ int   g_fill[NMAX];
__device__ int   g_col[EMAX];
__device__ int   g_bsum[64];           // per-block scan totals (<= 49 used)
__device__ float g_hs[(size_t)NMAX * HD];  // raw h = A @ W (gather source)
__device__ float g_h [(size_t)NMAX * HD];  // layer output

// ---------------- degree ----------------------------------------------------
__global__ void k_deg_zero(int n) {
    int i = blockIdx.x * blockDim.x + threadIdx.x;
    if (i < n) g_deg[i] = 0;
}

__global__ void k_deg_count(const int* __restrict__ dst, int e, int n) {
    int i = blockIdx.x * blockDim.x + threadIdx.x;
    if (i < e) {
        int d = dst[i];
        if ((unsigned)d < (unsigned)n) atomicAdd(&g_deg[d], 1);
    }
}

// ---------------- parallel exclusive scan of deg (2 kernels) ----------------
// scan1: warp-shuffle per-block scan -> partial rowptr + block totals + dinv
__global__ __launch_bounds__(1024) void k_scan1(int n) {
    __shared__ int wsum[32];
    int tid = threadIdx.x;
    int lane = tid & 31;
    int wid = tid >> 5;
    int i = blockIdx.x * 1024 + tid;
    int v = (i < n) ? g_deg[i] : 0;
    if (i < n) g_dinv[i] = rsqrtf((float)(v + 1));   // +1 self-loop
    // warp inclusive scan
    int inc = v;
#pragma unroll
    for (int o = 1; o < 32; o <<= 1) {
        int t = __shfl_up_sync(0xffffffffu, inc, o);
        if (lane >= o) inc += t;
    }
    if (lane == 31) wsum[wid] = inc;
    __syncthreads();
    if (wid == 0) {
        int wv = wsum[lane];
        int winc = wv;
#pragma unroll
        for (int o = 1; o < 32; o <<= 1) {
            int t = __shfl_up_sync(0xffffffffu, winc, o);
            if (lane >= o) winc += t;
        }
        wsum[lane] = winc - wv;   // exclusive warp offset
    }
    __syncthreads();
    int excl = (inc - v) + wsum[wid];
    if (i < n) g_rowptr[i] = excl;
    if (tid == 1023) g_bsum[blockIdx.x] = excl + v;   // block total
}

// scan3: parallel reduce of block totals, finalize rowptr + fill cursors
__global__ __launch_bounds__(1024) void k_scan3(int n) {
    __shared__ int off_s;
    int tid = threadIdx.x;
    if (tid < 32) {
        int bid = (int)blockIdx.x;
        int v = 0;
        if (tid < bid) v = g_bsum[tid];
        if (tid + 32 < bid) v += g_bsum[tid + 32];
#pragma unroll
        for (int o = 16; o >= 1; o >>= 1) v += __shfl_xor_sync(0xffffffffu, v, o);
        if (tid == 0) off_s = v;
    }
    __syncthreads();
    int i = blockIdx.x * 1024 + tid;
    if (i >= n) return;
    int rp = g_rowptr[i] + off_s;
    g_rowptr[i] = rp;
    g_fill[i] = rp;
    if (i == n - 1) g_rowptr[n] = rp + g_deg[i];
}

__global__ void k_fill(const int* __restrict__ src,
                       const int* __restrict__ dst, int e, int n) {
    int i = blockIdx.x * blockDim.x + threadIdx.x;
    if (i >= e) return;
    int d = dst[i];
    int s = src[i];
    if ((unsigned)d >= (unsigned)n || (unsigned)s >= (unsigned)n) return;
    int pos = atomicAdd(&g_fill[d], 1);
    if (pos < EMAX) g_col[pos] = s;
}

// ---------------- GEMM: g_hs = A @ W  (M x 128 @ 128 x 128), exact fp32 -----
// 128x128 block tile, 256 threads, 8x8 register tile, fma.rn.f32x2 (FFMA2).
template <int SRC>
__global__ __launch_bounds__(256) void k_gemm(const float* __restrict__ Ax,
                                              const float* __restrict__ W, int M) {
    const float* __restrict__ A = (SRC == 0) ? Ax : g_h;
    __shared__ float XsT[32][132];   // [k][m], padded
    __shared__ float Ws[32][128];    // [k][n]
    int tid = threadIdx.x;
    int row0 = blockIdx.x * 128;
    int tr = tid >> 4;    // 0..15 -> rows tr*8..tr*8+7
    int tc = tid & 15;    // 0..15 -> cols tc*8..tc*8+7

    unsigned long long acc[8][4];    // [i][j2]: packed pair of adjacent columns
#pragma unroll
    for (int i = 0; i < 8; i++)
#pragma unroll
        for (int j = 0; j < 4; j++) acc[i][j] = 0ULL;

    for (int k0 = 0; k0 < 128; k0 += 32) {
#pragma unroll
        for (int l = 0; l < 4; l++) {
            int f = tid + l * 256;        // 0..1023
            int k4 = f >> 7;              // 0..7 (k-group of 4)
            int m = f & 127;              // row within tile
            int grow = row0 + m;
            float4 v = make_float4(0.f, 0.f, 0.f, 0.f);
            if (grow < M) v = *(const float4*)&A[(size_t)grow * 128 + k0 + (k4 << 2)];
            XsT[(k4 << 2) + 0][m] = v.x;
            XsT[(k4 << 2) + 1][m] = v.y;
            XsT[(k4 << 2) + 2][m] = v.z;
            XsT[(k4 << 2) + 3][m] = v.w;
        }
#pragma unroll
        for (int l = 0; l < 4; l++) {
            int f = tid + l * 256;        // 0..1023
            int r = f >> 5;
            int c = (f & 31) << 2;
            *(float4*)&Ws[r][c] = *(const float4*)&W[(size_t)(k0 + r) * 128 + c];
        }
        __syncthreads();
#pragma unroll
        for (int kk = 0; kk < 32; kk++) {
            float a8[8];
            *(float4*)&a8[0] = *(const float4*)&XsT[kk][tr * 8];
            *(float4*)&a8[4] = *(const float4*)&XsT[kk][tr * 8 + 4];
            ulonglong2 t0 = *(const ulonglong2*)&Ws[kk][tc * 8];
            ulonglong2 t1 = *(const ulonglong2*)&Ws[kk][tc * 8 + 4];
            unsigned long long b4[4] = {t0.x, t0.y, t1.x, t1.y};
#pragma unroll
            for (int i = 0; i < 8; i++) {
                unsigned long long aa;
                unsigned int ai = __float_as_uint(a8[i]);
                asm("mov.b64 %0, {%1, %1};" : "=l"(aa) : "r"(ai));
#pragma unroll
                for (int j = 0; j < 4; j++)
                    asm("fma.rn.f32x2 %0, %1, %2, %3;"
                        : "=l"(acc[i][j])
                        : "l"(aa), "l"(b4[j]), "l"(acc[i][j]));
            }
        }
        __syncthreads();
    }
#pragma unroll
    for (int i = 0; i < 8; i++) {
        int row = row0 + tr * 8 + i;
        if (row < M) {
            *(ulonglong2*)&g_hs[(size_t)row * 128 + tc * 8] =
                make_ulonglong2(acc[i][0], acc[i][1]);
            *(ulonglong2*)&g_hs[(size_t)row * 128 + tc * 8 + 4] =
                make_ulonglong2(acc[i][2], acc[i][3]);
        }
    }
}

// ---------------- aggregation: one warp per node, CSR gather, 8-deep MLP ----
// (R8/R14 form: branch-free 8-wide main loop + scalar tail — measured best)
__global__ __launch_bounds__(256) void k_agg(const float* __restrict__ bias, int n) {
    int node = (int)((blockIdx.x * blockDim.x + threadIdx.x) >> 5);
    int lane = threadIdx.x & 31;
    if (node >= n) return;
    const float4* __restrict__ hs4 = (const float4*)g_hs;
    float dn = g_dinv[node];
    float4 hv = hs4[(size_t)node * 32 + lane];   // self-loop term
    float4 acc;
    acc.x = __fmul_rn(hv.x, dn);
    acc.y = __fmul_rn(hv.y, dn);
    acc.z = __fmul_rn(hv.z, dn);
    acc.w = __fmul_rn(hv.w, dn);
    int beg = __ldg(&g_rowptr[node]);
    int end = __ldg(&g_rowptr[node + 1]);
    int e = beg;
    for (; e + 8 <= end; e += 8) {
        int   s[8];
        float d[8];
        float4 v[8];
#pragma unroll
        for (int u = 0; u < 8; u++) s[u] = __ldg(&g_col[e + u]);
#pragma unroll
        for (int u = 0; u < 8; u++) d[u] = __ldg(&g_dinv[s[u]]);
#pragma unroll
        for (int u = 0; u < 8; u++) v[u] = __ldg(&hs4[(size_t)s[u] * 32 + lane]);
        float4 p0, p1;
        p0.x = (__fmul_rn(v[0].x, d[0]) + __fmul_rn(v[1].x, d[1])) + (__fmul_rn(v[2].x, d[2]) + __fmul_rn(v[3].x, d[3]));
        p0.y = (__fmul_rn(v[0].y, d[0]) + __fmul_rn(v[1].y, d[1])) + (__fmul_rn(v[2].y, d[2]) + __fmul_rn(v[3].y, d[3]));
        p0.z = (__fmul_rn(v[0].z, d[0]) + __fmul_rn(v[1].z, d[1])) + (__fmul_rn(v[2].z, d[2]) + __fmul_rn(v[3].z, d[3]));
        p0.w = (__fmul_rn(v[0].w, d[0]) + __fmul_rn(v[1].w, d[1])) + (__fmul_rn(v[2].w, d[2]) + __fmul_rn(v[3].w, d[3]));
        p1.x = (__fmul_rn(v[4].x, d[4]) + __fmul_rn(v[5].x, d[5])) + (__fmul_rn(v[6].x, d[6]) + __fmul_rn(v[7].x, d[7]));
        p1.y = (__fmul_rn(v[4].y, d[4]) + __fmul_rn(v[5].y, d[5])) + (__fmul_rn(v[6].y, d[6]) + __fmul_rn(v[7].y, d[7]));
        p1.z = (__fmul_rn(v[4].z, d[4]) + __fmul_rn(v[5].z, d[5])) + (__fmul_rn(v[6].z, d[6]) + __fmul_rn(v[7].z, d[7]));
        p1.w = (__fmul_rn(v[4].w, d[4]) + __fmul_rn(v[5].w, d[5])) + (__fmul_rn(v[6].w, d[6]) + __fmul_rn(v[7].w, d[7]));
        acc.x += p0.x + p1.x;
        acc.y += p0.y + p1.y;
        acc.z += p0.z + p1.z;
        acc.w += p0.w + p1.w;
    }
    for (; e < end; e++) {
        int s = __ldg(&g_col[e]);
        float ds = __ldg(&g_dinv[s]);
        float4 v = __ldg(&hs4[(size_t)s * 32 + lane]);
        acc.x += __fmul_rn(v.x, ds);
        acc.y += __fmul_rn(v.y, ds);
        acc.z += __fmul_rn(v.z, ds);
        acc.w += __fmul_rn(v.w, ds);
    }
    float4 bb = __ldg(&((const float4*)bias)[lane]);
    float4 o;
    o.x = fmaxf(fmaf(dn, acc.x, bb.x), 0.f);
    o.y = fmaxf(fmaf(dn, acc.y, bb.y), 0.f);
    o.z = fmaxf(fmaf(dn, acc.z, bb.z), 0.f);
    o.w = fmaxf(fmaf(dn, acc.w, bb.w), 0.f);
    ((float4*)g_h)[(size_t)node * 32 + lane] = o;
}

// ---------------- final: out = g_h @ Wc + bc  (M x 128 @ 128 x 16) ----------
__global__ __launch_bounds__(128) void k_final(const float* __restrict__ Wc,
                                               const float* __restrict__ bc,
                                               float* __restrict__ Out, int M) {
    __shared__ float Ws[128 * 16];
    __shared__ float bs[16];
    int tid = threadIdx.x;
    for (int i = tid; i < 128 * 16; i += 128) Ws[i] = Wc[i];
    if (tid < 16) bs[tid] = bc[tid];
    __syncthreads();
    int row = blockIdx.x * 128 + tid;
    if (row >= M) return;
    float acc[16];
#pragma unroll
    for (int j = 0; j < 16; j++) acc[j] = bs[j];
    const float4* h4 = (const float4*)(g_h + (size_t)row * 128);
#pragma unroll 4
    for (int k4 = 0; k4 < 32; k4++) {
        float4 xv = h4[k4];
#pragma unroll
        for (int kk = 0; kk < 4; kk++) {
            float xs = (kk == 0) ? xv.x : (kk == 1) ? xv.y : (kk == 2) ? xv.z : xv.w;
            int k = k4 * 4 + kk;
            float4 w0 = *(const float4*)&Ws[k * 16 + 0];
            float4 w1 = *(const float4*)&Ws[k * 16 + 4];
            float4 w2 = *(const float4*)&Ws[k * 16 + 8];
            float4 w3 = *(const float4*)&Ws[k * 16 + 12];
            acc[0]  += xs * w0.x; acc[1]  += xs * w0.y; acc[2]  += xs * w0.z; acc[3]  += xs * w0.w;
            acc[4]  += xs * w1.x; acc[5]  += xs * w1.y; acc[6]  += xs * w1.z; acc[7]  += xs * w1.w;
            acc[8]  += xs * w2.x; acc[9]  += xs * w2.y; acc[10] += xs * w2.z; acc[11] += xs * w2.w;
            acc[12] += xs * w3.x; acc[13] += xs * w3.y; acc[14] += xs * w3.z; acc[15] += xs * w3.w;
        }
    }
    float4* o4 = (float4*)(Out + (size_t)row * 16);
    o4[0] = make_float4(acc[0], acc[1], acc[2], acc[3]);
    o4[1] = make_float4(acc[4], acc[5], acc[6], acc[7]);
    o4[2] = make_float4(acc[8], acc[9], acc[10], acc[11]);
    o4[3] = make_float4(acc[12], acc[13], acc[14], acc[15]);
}

// ---------------- launcher (R8 structure: prep ∥ gemm1) ----------------------
extern "C" void kernel_launch(void* const* d_in, const int* in_sizes, int n_in,
                              void* d_out, int out_size) {
    const float* x  = (const float*)d_in[0];
    const int*   ei = (const int*)d_in[1];      // int32 (JAX demotes int64)
    const float* W1 = (const float*)d_in[2];
    const float* b1 = (const float*)d_in[3];
    const float* W2 = (const float*)d_in[4];
    const float* b2 = (const float*)d_in[5];
    const float* Wc = (const float*)d_in[6];
    const float* bc = (const float*)d_in[7];
    float* out = (float*)d_out;

    int n = in_sizes[0] / HD;       // 50000
    int e = in_sizes[1] / 2;        // 1600000
    const int* srcp = ei;
    const int* dstp = ei + e;

    int gn256 = (n + 255) / 256;
    int ge256 = (e + 255) / 256;
    int nb = (n + 1023) / 1024;     // 49 scan blocks

    // one-time host-side stream/event setup (identical GPU work every call)
    static cudaStream_t s_side = (cudaStream_t)0;
    static cudaEvent_t  ev_fork = nullptr, ev_join = nullptr;
    static int s_init = 0;
    if (!s_init) {
        cudaStream_t st;
        cudaEvent_t e0, e1;
        if (cudaStreamCreateWithFlags(&st, cudaStreamNonBlocking) == cudaSuccess &&
            cudaEventCreateWithFlags(&e0, cudaEventDisableTiming) == cudaSuccess &&
            cudaEventCreateWithFlags(&e1, cudaEventDisableTiming) == cudaSuccess) {
            s_side = st; ev_fork = e0; ev_join = e1;
        }
        s_init = 1;
    }
    cudaStream_t sp = s_side;           // prep stream (falls back to 0)
    bool overlap = (s_side != (cudaStream_t)0);

    if (overlap) {
        cudaEventRecord(ev_fork, 0);
        cudaStreamWaitEvent(s_side, ev_fork, 0);
    }

    // CSR build on side stream (runs concurrently with gemm1)
    k_deg_zero<<<gn256, 256, 0, sp>>>(n);
    k_deg_count<<<ge256, 256, 0, sp>>>(dstp, e, n);
    k_scan1<<<nb, 1024, 0, sp>>>(n);
    k_scan3<<<nb, 1024, 0, sp>>>(n);
    k_fill<<<ge256, 256, 0, sp>>>(srcp, dstp, e, n);

    if (overlap) cudaEventRecord(ev_join, s_side);

    int gemm_blocks = (n + 127) / 128;
    int agg_blocks  = (n + 7) / 8;      // 8 warps (nodes) per 256-thread block

    // layer 1 (gemm1 independent of CSR build)
    k_gemm<0><<<gemm_blocks, 256>>>(x, W1, n);
    if (overlap) cudaStreamWaitEvent(0, ev_join, 0);
    k_agg<<<agg_blocks, 256>>>(b1, n);
    // layer 2
    k_gemm<1><<<gemm_blocks, 256>>>(x, W2, n);
    k_agg<<<agg_blocks, 256>>>(b2, n);
    // classifier head
    k_final<<<(n + 127) / 128, 128>>>(Wc, bc, out, n);
}